// round 9
// baseline (speedup 1.0000x reference)
#include <cuda_runtime.h>
#include <cstdint>

// coordinates: (3, 64,64,64) fp32   -> N = 262144
// images:      (8, 32, 480, 480) fp32
// transformations: (8, 3, 4) fp32
// T_cw:        (8, 4, 4) fp32
// out:         (8, 37, 262144) fp32   (C=32 feats, depth, validity, viewdir xyz)

namespace {
constexpr int kI = 8;
constexpr int kC = 32;
constexpr int kH = 480;
constexpr int kW = 480;
constexpr int kN = 64 * 64 * 64;          // 262144
constexpr int kHW = kH * kW;              // 230400
constexpr int kOutC = kC + 5;             // 37
constexpr int TPB = 256;
constexpr int PPT = 4;                    // points per thread (float4 stores)
}

// Non-FMA, ascending-l dot (bit-matches XLA loop emitter, verified R3):
__device__ __forceinline__ float dot4_nofma(float a0, float a1, float a2, float a3,
                                            float x, float y, float z)
{
    float s = __fmul_rn(a0, x);
    s = __fadd_rn(s, __fmul_rn(a1, y));
    s = __fadd_rn(s, __fmul_rn(a2, z));
    s = __fadd_rn(s, a3);
    return s;
}

__global__ __launch_bounds__(TPB, 4)   // 64 regs / 32-load batch: proven optimum (R6)
void base_smear_kernel(const float* __restrict__ coords,
                       const float* __restrict__ images,
                       const float* __restrict__ trans,
                       const float* __restrict__ tcw,
                       float* __restrict__ out)
{
    const int i = blockIdx.y;
    const int n = (blockIdx.x * TPB + threadIdx.x) * PPT;
    if (n >= kN) return;

    // ---- load 4 points (coalesced float4) ----
    const float4 cx = *reinterpret_cast<const float4*>(coords + n);
    const float4 cy = *reinterpret_cast<const float4*>(coords + kN + n);
    const float4 cz = *reinterpret_cast<const float4*>(coords + 2 * kN + n);

    // ---- per-image parameters (uniform across warp -> broadcast) ----
    const float* T = trans + i * 12;
    const float t00 = __ldg(T + 0), t01 = __ldg(T + 1), t02 = __ldg(T + 2),  t03 = __ldg(T + 3);
    const float t10 = __ldg(T + 4), t11 = __ldg(T + 5), t12 = __ldg(T + 6),  t13 = __ldg(T + 7);
    const float t20 = __ldg(T + 8), t21 = __ldg(T + 9), t22 = __ldg(T + 10), t23 = __ldg(T + 11);

    const float* M = tcw + i * 16;
    const float d0 = __ldg(M + 8), d1 = __ldg(M + 9), d2 = __ldg(M + 10), d3 = __ldg(M + 11);
    const float r00 = __ldg(M + 0), r01 = __ldg(M + 1), r02 = __ldg(M + 2),  tx = __ldg(M + 3);
    const float r10 = __ldg(M + 4), r11 = __ldg(M + 5), r12 = __ldg(M + 6),  ty = __ldg(M + 7);
    const float r20 = __ldg(M + 8), r21 = __ldg(M + 9), r22 = __ldg(M + 10), tz = __ldg(M + 11);
    const float ccx = -__fadd_rn(__fadd_rn(__fmul_rn(r00, tx), __fmul_rn(r10, ty)), __fmul_rn(r20, tz));
    const float ccy = -__fadd_rn(__fadd_rn(__fmul_rn(r01, tx), __fmul_rn(r11, ty)), __fmul_rn(r21, tz));
    const float ccz = -__fadd_rn(__fadd_rn(__fmul_rn(r02, tx), __fmul_rn(r12, ty)), __fmul_rn(r22, tz));

    const float px[PPT] = {cx.x, cx.y, cx.z, cx.w};
    const float py[PPT] = {cy.x, cy.y, cy.z, cy.w};
    const float pz[PPT] = {cz.x, cz.y, cz.z, cz.w};

    int  off[PPT];
    bool valid[PPT];
    float depth[PPT], vdx[PPT], vdy[PPT], vdz[PPT];

#pragma unroll
    for (int p = 0; p < PPT; ++p) {
        const float X = px[p], Y = py[p], Z = pz[p];

        const float p0 = dot4_nofma(t00, t01, t02, t03, X, Y, Z);
        const float p1 = dot4_nofma(t10, t11, t12, t13, X, Y, Z);
        const float p2 = dot4_nofma(t20, t21, t22, t23, X, Y, Z);

        const float zs = (fabsf(p2) < 1e-8f) ? 1e-8f : p2;
        const float u = __fdiv_rn(p0, zs);
        const float v = __fdiv_rn(p1, zs);

        valid[p] = (p2 > 0.0f) & (u >= 0.0f) & (u <= (float)(kW - 1)) &
                   (v >= 0.0f) & (v <= (float)(kH - 1));

        const int ui = (int)fminf(fmaxf(rintf(u), 0.0f), (float)(kW - 1));
        const int vi = (int)fminf(fmaxf(rintf(v), 0.0f), (float)(kH - 1));
        off[p] = vi * kW + ui;

        depth[p] = dot4_nofma(d0, d1, d2, d3, X, Y, Z);

        const float dx = __fadd_rn(X, -ccx), dy = __fadd_rn(Y, -ccy), dz = __fadd_rn(Z, -ccz);
        float nrm = sqrtf(__fadd_rn(__fadd_rn(__fmul_rn(dx, dx), __fmul_rn(dy, dy)), __fmul_rn(dz, dz)));
        nrm = fmaxf(nrm, 1e-8f);
        vdx[p] = __fdiv_rn(dx, nrm);
        vdy[p] = __fdiv_rn(dy, nrm);
        vdz[p] = __fdiv_rn(dz, nrm);
    }

    float* ob = out + (size_t)i * kOutC * kN + n;
    const float* img = images + (size_t)i * kC * kHW;

    // ---- issue FIRST gather batch (cb=0): its ~250cy latency is covered by the
    //      tail-channel stores below ----
    float f[8][4];
#pragma unroll
    for (int c = 0; c < 8; ++c) {
        const float* ic = img + (size_t)c * kHW;
        f[c][0] = valid[0] ? __ldcg(ic + off[0]) : 0.0f;
        f[c][1] = valid[1] ? __ldcg(ic + off[1]) : 0.0f;
        f[c][2] = valid[2] ? __ldcg(ic + off[2]) : 0.0f;
        f[c][3] = valid[3] ? __ldcg(ic + off[3]) : 0.0f;
    }

    // ---- tail channels (independent of gathers; fill the latency shadow) ----
    {
        float4 d = {depth[0], depth[1], depth[2], depth[3]};
        __stcs(reinterpret_cast<float4*>(ob + (size_t)kC * kN), d);

        float4 vld = {valid[0] ? 1.0f : 0.0f, valid[1] ? 1.0f : 0.0f,
                      valid[2] ? 1.0f : 0.0f, valid[3] ? 1.0f : 0.0f};
        __stcs(reinterpret_cast<float4*>(ob + (size_t)(kC + 1) * kN), vld);

        float4 a = {vdx[0], vdx[1], vdx[2], vdx[3]};
        __stcs(reinterpret_cast<float4*>(ob + (size_t)(kC + 2) * kN), a);
        float4 b = {vdy[0], vdy[1], vdy[2], vdy[3]};
        __stcs(reinterpret_cast<float4*>(ob + (size_t)(kC + 3) * kN), b);
        float4 g = {vdz[0], vdz[1], vdz[2], vdz[3]};
        __stcs(reinterpret_cast<float4*>(ob + (size_t)(kC + 4) * kN), g);
    }

    // ---- drain batch 0, then remaining batches of 8 channels x 4 points ----
#pragma unroll
    for (int cb = 0; cb < kC; cb += 8) {
        if (cb > 0) {
#pragma unroll
            for (int c = 0; c < 8; ++c) {
                const float* ic = img + (size_t)(cb + c) * kHW;
                f[c][0] = valid[0] ? __ldcg(ic + off[0]) : 0.0f;
                f[c][1] = valid[1] ? __ldcg(ic + off[1]) : 0.0f;
                f[c][2] = valid[2] ? __ldcg(ic + off[2]) : 0.0f;
                f[c][3] = valid[3] ? __ldcg(ic + off[3]) : 0.0f;
            }
        }
#pragma unroll
        for (int c = 0; c < 8; ++c) {
            float4 v4 = {f[c][0], f[c][1], f[c][2], f[c][3]};
            __stcs(reinterpret_cast<float4*>(ob + (size_t)(cb + c) * kN), v4);
        }
    }
}

extern "C" void kernel_launch(void* const* d_in, const int* in_sizes, int n_in,
                              void* d_out, int out_size)
{
    const float* coords = (const float*)d_in[0];
    const float* images = (const float*)d_in[1];
    const float* trans  = (const float*)d_in[2];
    const float* tcw    = (const float*)d_in[3];
    float* out = (float*)d_out;

    dim3 grid(kN / (TPB * PPT), kI, 1);   // 256 x 8 blocks
    base_smear_kernel<<<grid, TPB>>>(coords, images, trans, tcw, out);
}

// round 10
// speedup vs baseline: 1.2330x; 1.2330x over previous
#include <cuda_runtime.h>
#include <cstdint>

// coordinates: (3, 64,64,64) fp32   -> N = 262144
// images:      (8, 32, 480, 480) fp32
// transformations: (8, 3, 4) fp32
// T_cw:        (8, 4, 4) fp32
// out:         (8, 37, 262144) fp32   (C=32 feats, depth, validity, viewdir xyz)

namespace {
constexpr int kI = 8;
constexpr int kC = 32;
constexpr int kH = 480;
constexpr int kW = 480;
constexpr int kN = 64 * 64 * 64;          // 262144
constexpr int kHW = kH * kW;              // 230400
constexpr int kOutC = kC + 5;             // 37
constexpr int TPB = 256;
constexpr int PPT = 4;                    // points per thread (float4 stores)
}

// Non-FMA, ascending-l dot (bit-matches XLA loop emitter, verified R3):
__device__ __forceinline__ float dot4_nofma(float a0, float a1, float a2, float a3,
                                            float x, float y, float z)
{
    float s = __fmul_rn(a0, x);
    s = __fadd_rn(s, __fmul_rn(a1, y));
    s = __fadd_rn(s, __fmul_rn(a2, z));
    s = __fadd_rn(s, a3);
    return s;
}

__global__ __launch_bounds__(TPB, 4)   // 64 regs / 32-load batch: proven optimum (R6)
void base_smear_kernel(const float* __restrict__ coords,
                       const float* __restrict__ images,
                       const float* __restrict__ trans,
                       const float* __restrict__ tcw,
                       float* __restrict__ out)
{
    const int i = blockIdx.y;
    const int n = (blockIdx.x * TPB + threadIdx.x) * PPT;
    if (n >= kN) return;

    // ---- load 4 points (coalesced float4) ----
    const float4 cx = *reinterpret_cast<const float4*>(coords + n);
    const float4 cy = *reinterpret_cast<const float4*>(coords + kN + n);
    const float4 cz = *reinterpret_cast<const float4*>(coords + 2 * kN + n);

    // ---- per-image parameters (uniform across warp -> broadcast) ----
    const float* T = trans + i * 12;
    const float t00 = __ldg(T + 0), t01 = __ldg(T + 1), t02 = __ldg(T + 2),  t03 = __ldg(T + 3);
    const float t10 = __ldg(T + 4), t11 = __ldg(T + 5), t12 = __ldg(T + 6),  t13 = __ldg(T + 7);
    const float t20 = __ldg(T + 8), t21 = __ldg(T + 9), t22 = __ldg(T + 10), t23 = __ldg(T + 11);

    const float* M = tcw + i * 16;
    const float d0 = __ldg(M + 8), d1 = __ldg(M + 9), d2 = __ldg(M + 10), d3 = __ldg(M + 11);
    const float r00 = __ldg(M + 0), r01 = __ldg(M + 1), r02 = __ldg(M + 2),  tx = __ldg(M + 3);
    const float r10 = __ldg(M + 4), r11 = __ldg(M + 5), r12 = __ldg(M + 6),  ty = __ldg(M + 7);
    const float r20 = __ldg(M + 8), r21 = __ldg(M + 9), r22 = __ldg(M + 10), tz = __ldg(M + 11);
    const float ccx = -__fadd_rn(__fadd_rn(__fmul_rn(r00, tx), __fmul_rn(r10, ty)), __fmul_rn(r20, tz));
    const float ccy = -__fadd_rn(__fadd_rn(__fmul_rn(r01, tx), __fmul_rn(r11, ty)), __fmul_rn(r21, tz));
    const float ccz = -__fadd_rn(__fadd_rn(__fmul_rn(r02, tx), __fmul_rn(r12, ty)), __fmul_rn(r22, tz));

    const float px[PPT] = {cx.x, cx.y, cx.z, cx.w};
    const float py[PPT] = {cy.x, cy.y, cy.z, cy.w};
    const float pz[PPT] = {cz.x, cz.y, cz.z, cz.w};

    int  off[PPT];
    bool valid[PPT];
    float depth[PPT], vdx[PPT], vdy[PPT], vdz[PPT];

#pragma unroll
    for (int p = 0; p < PPT; ++p) {
        const float X = px[p], Y = py[p], Z = pz[p];

        const float p0 = dot4_nofma(t00, t01, t02, t03, X, Y, Z);
        const float p1 = dot4_nofma(t10, t11, t12, t13, X, Y, Z);
        const float p2 = dot4_nofma(t20, t21, t22, t23, X, Y, Z);

        const float zs = (fabsf(p2) < 1e-8f) ? 1e-8f : p2;
        const float u = __fdiv_rn(p0, zs);
        const float v = __fdiv_rn(p1, zs);

        valid[p] = (p2 > 0.0f) & (u >= 0.0f) & (u <= (float)(kW - 1)) &
                   (v >= 0.0f) & (v <= (float)(kH - 1));

        const int ui = (int)fminf(fmaxf(rintf(u), 0.0f), (float)(kW - 1));
        const int vi = (int)fminf(fmaxf(rintf(v), 0.0f), (float)(kH - 1));
        off[p] = vi * kW + ui;

        depth[p] = dot4_nofma(d0, d1, d2, d3, X, Y, Z);

        const float dx = __fadd_rn(X, -ccx), dy = __fadd_rn(Y, -ccy), dz = __fadd_rn(Z, -ccz);
        float nrm = sqrtf(__fadd_rn(__fadd_rn(__fmul_rn(dx, dx), __fmul_rn(dy, dy)), __fmul_rn(dz, dz)));
        nrm = fmaxf(nrm, 1e-8f);
        vdx[p] = __fdiv_rn(dx, nrm);
        vdy[p] = __fdiv_rn(dy, nrm);
        vdz[p] = __fdiv_rn(dz, nrm);
    }

    float* ob = out + (size_t)i * kOutC * kN + n;
    const float* img = images + (size_t)i * kC * kHW;

    // ---- issue FIRST gather batch (cb=0) early; L1-cached (__ldg) — the hot
    //      projected region is L1-resident (R9 lesson) ----
    float f[8][4];
#pragma unroll
    for (int c = 0; c < 8; ++c) {
        const float* ic = img + (size_t)c * kHW;
        f[c][0] = valid[0] ? __ldg(ic + off[0]) : 0.0f;
        f[c][1] = valid[1] ? __ldg(ic + off[1]) : 0.0f;
        f[c][2] = valid[2] ? __ldg(ic + off[2]) : 0.0f;
        f[c][3] = valid[3] ? __ldg(ic + off[3]) : 0.0f;
    }

    // ---- tail channels (independent of gathers; fill the latency shadow) ----
    {
        float4 d = {depth[0], depth[1], depth[2], depth[3]};
        __stcs(reinterpret_cast<float4*>(ob + (size_t)kC * kN), d);

        float4 vld = {valid[0] ? 1.0f : 0.0f, valid[1] ? 1.0f : 0.0f,
                      valid[2] ? 1.0f : 0.0f, valid[3] ? 1.0f : 0.0f};
        __stcs(reinterpret_cast<float4*>(ob + (size_t)(kC + 1) * kN), vld);

        float4 a = {vdx[0], vdx[1], vdx[2], vdx[3]};
        __stcs(reinterpret_cast<float4*>(ob + (size_t)(kC + 2) * kN), a);
        float4 b = {vdy[0], vdy[1], vdy[2], vdy[3]};
        __stcs(reinterpret_cast<float4*>(ob + (size_t)(kC + 3) * kN), b);
        float4 g = {vdz[0], vdz[1], vdz[2], vdz[3]};
        __stcs(reinterpret_cast<float4*>(ob + (size_t)(kC + 4) * kN), g);
    }

    // ---- drain batch 0, then remaining batches of 8 channels x 4 points ----
#pragma unroll
    for (int cb = 0; cb < kC; cb += 8) {
        if (cb > 0) {
#pragma unroll
            for (int c = 0; c < 8; ++c) {
                const float* ic = img + (size_t)(cb + c) * kHW;
                f[c][0] = valid[0] ? __ldg(ic + off[0]) : 0.0f;
                f[c][1] = valid[1] ? __ldg(ic + off[1]) : 0.0f;
                f[c][2] = valid[2] ? __ldg(ic + off[2]) : 0.0f;
                f[c][3] = valid[3] ? __ldg(ic + off[3]) : 0.0f;
            }
        }
#pragma unroll
        for (int c = 0; c < 8; ++c) {
            float4 v4 = {f[c][0], f[c][1], f[c][2], f[c][3]};
            __stcs(reinterpret_cast<float4*>(ob + (size_t)(cb + c) * kN), v4);
        }
    }
}

extern "C" void kernel_launch(void* const* d_in, const int* in_sizes, int n_in,
                              void* d_out, int out_size)
{
    const float* coords = (const float*)d_in[0];
    const float* images = (const float*)d_in[1];
    const float* trans  = (const float*)d_in[2];
    const float* tcw    = (const float*)d_in[3];
    float* out = (float*)d_out;

    dim3 grid(kN / (TPB * PPT), kI, 1);   // 256 x 8 blocks
    base_smear_kernel<<<grid, TPB>>>(coords, images, trans, tcw, out);
}

// round 11
// speedup vs baseline: 1.2767x; 1.0354x over previous
#include <cuda_runtime.h>
#include <cstdint>

// coordinates: (3, 64,64,64) fp32   -> N = 262144
// images:      (8, 32, 480, 480) fp32  (236 MB)
// transformations: (8, 3, 4) fp32
// T_cw:        (8, 4, 4) fp32
// out:         (8, 37, 262144) fp32   (C=32 feats, depth, validity, viewdir xyz)

namespace {
constexpr int kI = 8;
constexpr int kC = 32;
constexpr int kH = 480;
constexpr int kW = 480;
constexpr int kN = 64 * 64 * 64;          // 262144
constexpr int kHW = kH * kW;              // 230400
constexpr int kOutC = kC + 5;             // 37
constexpr int TPB = 256;
constexpr int PPT = 4;                    // points per thread (float4 stores)
constexpr int kZG = 4;                    // channel groups (8 channels each)
constexpr int kCG = kC / kZG;             // 8
}

// Non-FMA, ascending-l dot (bit-matches XLA loop emitter, verified R3):
__device__ __forceinline__ float dot4_nofma(float a0, float a1, float a2, float a3,
                                            float x, float y, float z)
{
    float s = __fmul_rn(a0, x);
    s = __fadd_rn(s, __fmul_rn(a1, y));
    s = __fadd_rn(s, __fmul_rn(a2, z));
    s = __fadd_rn(s, a3);
    return s;
}

__global__ __launch_bounds__(TPB, 5)   // <=51 regs: gather phase has tiny live set now
void base_smear_kernel(const float* __restrict__ coords,
                       const float* __restrict__ images,
                       const float* __restrict__ trans,
                       const float* __restrict__ tcw,
                       float* __restrict__ out)
{
    const int i  = blockIdx.y;
    const int zg = blockIdx.z;            // channel group: handles channels [zg*8, zg*8+8)
    const int n  = (blockIdx.x * TPB + threadIdx.x) * PPT;
    if (n >= kN) return;

    // ---- load 4 points (coalesced float4; coords are 3MB -> L2 resident) ----
    const float4 cx = *reinterpret_cast<const float4*>(coords + n);
    const float4 cy = *reinterpret_cast<const float4*>(coords + kN + n);
    const float4 cz = *reinterpret_cast<const float4*>(coords + 2 * kN + n);

    // ---- projection matrix (uniform across block -> broadcast) ----
    const float* T = trans + i * 12;
    const float t00 = __ldg(T + 0), t01 = __ldg(T + 1), t02 = __ldg(T + 2),  t03 = __ldg(T + 3);
    const float t10 = __ldg(T + 4), t11 = __ldg(T + 5), t12 = __ldg(T + 6),  t13 = __ldg(T + 7);
    const float t20 = __ldg(T + 8), t21 = __ldg(T + 9), t22 = __ldg(T + 10), t23 = __ldg(T + 11);

    const float px[PPT] = {cx.x, cx.y, cx.z, cx.w};
    const float py[PPT] = {cy.x, cy.y, cy.z, cy.w};
    const float pz[PPT] = {cz.x, cz.y, cz.z, cz.w};

    int  off[PPT];
    bool valid[PPT];

#pragma unroll
    for (int p = 0; p < PPT; ++p) {
        const float X = px[p], Y = py[p], Z = pz[p];

        const float p0 = dot4_nofma(t00, t01, t02, t03, X, Y, Z);
        const float p1 = dot4_nofma(t10, t11, t12, t13, X, Y, Z);
        const float p2 = dot4_nofma(t20, t21, t22, t23, X, Y, Z);

        const float zs = (fabsf(p2) < 1e-8f) ? 1e-8f : p2;
        const float u = __fdiv_rn(p0, zs);
        const float v = __fdiv_rn(p1, zs);

        valid[p] = (p2 > 0.0f) & (u >= 0.0f) & (u <= (float)(kW - 1)) &
                   (v >= 0.0f) & (v <= (float)(kH - 1));

        const int ui = (int)fminf(fmaxf(rintf(u), 0.0f), (float)(kW - 1));
        const int vi = (int)fminf(fmaxf(rintf(v), 0.0f), (float)(kH - 1));
        off[p] = vi * kW + ui;
    }

    float* ob = out + (size_t)i * kOutC * kN + n;

    // ---- channel-group 0 blocks also produce the 5 tail channels ----
    if (zg == 0) {
        const float* M = tcw + i * 16;
        const float d0 = __ldg(M + 8), d1 = __ldg(M + 9), d2 = __ldg(M + 10), d3 = __ldg(M + 11);
        const float r00 = __ldg(M + 0), r01 = __ldg(M + 1), r02 = __ldg(M + 2),  tx = __ldg(M + 3);
        const float r10 = __ldg(M + 4), r11 = __ldg(M + 5), r12 = __ldg(M + 6),  ty = __ldg(M + 7);
        const float r20 = __ldg(M + 8), r21 = __ldg(M + 9), r22 = __ldg(M + 10), tz = __ldg(M + 11);
        const float ccx = -__fadd_rn(__fadd_rn(__fmul_rn(r00, tx), __fmul_rn(r10, ty)), __fmul_rn(r20, tz));
        const float ccy = -__fadd_rn(__fadd_rn(__fmul_rn(r01, tx), __fmul_rn(r11, ty)), __fmul_rn(r21, tz));
        const float ccz = -__fadd_rn(__fadd_rn(__fmul_rn(r02, tx), __fmul_rn(r12, ty)), __fmul_rn(r22, tz));

        float depth[PPT], vdx[PPT], vdy[PPT], vdz[PPT];
#pragma unroll
        for (int p = 0; p < PPT; ++p) {
            const float X = px[p], Y = py[p], Z = pz[p];
            depth[p] = dot4_nofma(d0, d1, d2, d3, X, Y, Z);
            const float dx = __fadd_rn(X, -ccx), dy = __fadd_rn(Y, -ccy), dz = __fadd_rn(Z, -ccz);
            float nrm = sqrtf(__fadd_rn(__fadd_rn(__fmul_rn(dx, dx), __fmul_rn(dy, dy)), __fmul_rn(dz, dz)));
            nrm = fmaxf(nrm, 1e-8f);
            vdx[p] = __fdiv_rn(dx, nrm);
            vdy[p] = __fdiv_rn(dy, nrm);
            vdz[p] = __fdiv_rn(dz, nrm);
        }

        float4 d = {depth[0], depth[1], depth[2], depth[3]};
        __stcs(reinterpret_cast<float4*>(ob + (size_t)kC * kN), d);
        float4 vld = {valid[0] ? 1.0f : 0.0f, valid[1] ? 1.0f : 0.0f,
                      valid[2] ? 1.0f : 0.0f, valid[3] ? 1.0f : 0.0f};
        __stcs(reinterpret_cast<float4*>(ob + (size_t)(kC + 1) * kN), vld);
        float4 a = {vdx[0], vdx[1], vdx[2], vdx[3]};
        __stcs(reinterpret_cast<float4*>(ob + (size_t)(kC + 2) * kN), a);
        float4 b = {vdy[0], vdy[1], vdy[2], vdy[3]};
        __stcs(reinterpret_cast<float4*>(ob + (size_t)(kC + 3) * kN), b);
        float4 g = {vdz[0], vdz[1], vdz[2], vdz[3]};
        __stcs(reinterpret_cast<float4*>(ob + (size_t)(kC + 4) * kN), g);
    }

    // ---- this block's 8 channels: all 32 LDGs in flight, tiny live set ----
    const float* img = images + (size_t)i * kC * kHW + (size_t)zg * kCG * kHW;

    float f[kCG][4];
#pragma unroll
    for (int c = 0; c < kCG; ++c) {
        const float* ic = img + (size_t)c * kHW;
        f[c][0] = valid[0] ? __ldg(ic + off[0]) : 0.0f;
        f[c][1] = valid[1] ? __ldg(ic + off[1]) : 0.0f;
        f[c][2] = valid[2] ? __ldg(ic + off[2]) : 0.0f;
        f[c][3] = valid[3] ? __ldg(ic + off[3]) : 0.0f;
    }

    float* obg = ob + (size_t)zg * kCG * kN;
#pragma unroll
    for (int c = 0; c < kCG; ++c) {
        float4 v4 = {f[c][0], f[c][1], f[c][2], f[c][3]};
        __stcs(reinterpret_cast<float4*>(obg + (size_t)c * kN), v4);
    }
}

extern "C" void kernel_launch(void* const* d_in, const int* in_sizes, int n_in,
                              void* d_out, int out_size)
{
    const float* coords = (const float*)d_in[0];
    const float* images = (const float*)d_in[1];
    const float* trans  = (const float*)d_in[2];
    const float* tcw    = (const float*)d_in[3];
    float* out = (float*)d_out;

    dim3 grid(kN / (TPB * PPT), kI, kZG);   // 256 x 8 x 4 blocks
    base_smear_kernel<<<grid, TPB>>>(coords, images, trans, tcw, out);
}